// round 1
// baseline (speedup 1.0000x reference)
#include <cuda_runtime.h>
#include <math_constants.h>

// Problem shape (fixed by reference): B=8, N=M=8192, D=3, fp32 scalar out.
#define BB 8
#define NN 8192
#define MM 8192
#define RPT 8                       // gt rows per thread
#define ROWS_PER_BLOCK 128          // 16 ty-lanes * RPT
#define NUM_RB (NN / ROWS_PER_BLOCK) // 64 row-blocks per batch
#define STAGE 256                   // preds staged in smem per sync round
#define CHUNK 64                    // cols processed per inner chunk (16 tx * 4)

// Static scratch (no allocations allowed).
__device__ float4 g_gt4[BB * NN];                    // (-x,-y,-z, 0.5*|x|^2)
__device__ float4 g_pr4[BB * MM];                    // ( x, y, z, 0.5*|y|^2)
__device__ float  g_minx[BB * NN];                   // per-gt min (d'/1 form)
__device__ float  g_cpart[(size_t)NUM_RB * BB * MM]; // per-rowblock partial col mins (16MB)
__device__ float  g_part[512];                       // block partial sums

// ---------------------------------------------------------------------------
// Pack points into float4 with w = 0.5*norm^2; negate gt coords so the inner
// loop is pure FMA:  d' = gw + pw + (-gx)*px + (-gy)*py + (-gz)*pz = d^2/2.
// ---------------------------------------------------------------------------
__global__ void prep_kernel(const float* __restrict__ gts,
                            const float* __restrict__ preds) {
    int i = blockIdx.x * blockDim.x + threadIdx.x;
    if (i < BB * NN) {
        float x = gts[3 * i + 0], y = gts[3 * i + 1], z = gts[3 * i + 2];
        g_gt4[i] = make_float4(-x, -y, -z, 0.5f * (x * x + y * y + z * z));
    }
    if (i < BB * MM) {
        float x = preds[3 * i + 0], y = preds[3 * i + 1], z = preds[3 * i + 2];
        g_pr4[i] = make_float4(x, y, z, 0.5f * (x * x + y * y + z * z));
    }
}

// ---------------------------------------------------------------------------
// Fused tiled kernel: each block = (batch b, row-block rb) of 128 gt rows,
// iterates over all M preds. Computes d' once per pair; updates register
// row-mins and half-warp-reduced col-mins.
// Thread layout: tx = tid/16 (column group = one half-warp), ty = tid%16.
// ---------------------------------------------------------------------------
__global__ void __launch_bounds__(256, 3) chamfer_main_kernel() {
    __shared__ float4 sp[STAGE];
    __shared__ float rowred[16][ROWS_PER_BLOCK];

    const int tid = threadIdx.x;
    const int tx = tid >> 4;   // 0..15 (half-warp id within block)
    const int ty = tid & 15;   // 0..15 (lane within half-warp)
    const int b  = blockIdx.x / NUM_RB;
    const int rb = blockIdx.x % NUM_RB;
    const int rowbase = rb * ROWS_PER_BLOCK;

    float4 g[RPT];
    float rmin[RPT];
#pragma unroll
    for (int i = 0; i < RPT; i++) {
        g[i] = g_gt4[b * NN + rowbase + ty + 16 * i];
        rmin[i] = CUDART_INF_F;
    }

    for (int s = 0; s < MM; s += STAGE) {
        __syncthreads();                       // previous stage fully consumed
        sp[tid] = g_pr4[b * MM + s + tid];     // cooperative stage load
        __syncthreads();

#pragma unroll
        for (int c = 0; c < STAGE / CHUNK; c++) {
            const int colb = c * CHUNK + tx * 4;
            float4 p[4];
            float cmin[4];
#pragma unroll
            for (int j = 0; j < 4; j++) {
                p[j] = sp[colb + j];           // broadcast within half-warp
                cmin[j] = CUDART_INF_F;
            }
#pragma unroll
            for (int i = 0; i < RPT; i++) {
#pragma unroll
                for (int j = 0; j < 4; j++) {
                    float t = g[i].w + p[j].w;
                    t = fmaf(g[i].x, p[j].x, t);
                    t = fmaf(g[i].y, p[j].y, t);
                    t = fmaf(g[i].z, p[j].z, t);
                    rmin[i] = fminf(rmin[i], t);
                    cmin[j] = fminf(cmin[j], t);
                }
            }
            // Reduce col mins across the 16 lanes of this half-warp
            // (xor < 16 keeps the butterfly inside each 16-lane half).
#pragma unroll
            for (int o = 8; o >= 1; o >>= 1) {
#pragma unroll
                for (int j = 0; j < 4; j++)
                    cmin[j] = fminf(cmin[j],
                                    __shfl_xor_sync(0xFFFFFFFFu, cmin[j], o, 32));
            }
            if (ty == 0) {
                const int col = s + colb;
                float4* dst = reinterpret_cast<float4*>(
                    &g_cpart[(size_t)rb * (BB * MM) + (size_t)b * MM + col]);
                *dst = make_float4(cmin[0], cmin[1], cmin[2], cmin[3]);
            }
        }
    }

    // Finalize row mins: reduce across the 16 tx groups.
#pragma unroll
    for (int i = 0; i < RPT; i++) rowred[tx][ty + 16 * i] = rmin[i];
    __syncthreads();
    if (tid < ROWS_PER_BLOCK) {
        float v = rowred[0][tid];
#pragma unroll
        for (int k = 1; k < 16; k++) v = fminf(v, rowred[k][tid]);
        g_minx[b * NN + rowbase + tid] = v;
    }
}

// ---------------------------------------------------------------------------
// Reduce: blocks 0..255 sum the row mins; blocks 256..511 min-reduce the
// 64 row-block partials per pred column, then sum. All deterministic trees.
// d' = d^2/2, clamp tiny negatives like the reference: contribution = max(2v,0).
// ---------------------------------------------------------------------------
__global__ void reduce_kernel() {
    __shared__ float sred[256];
    const int blk = blockIdx.x;
    const int tid = threadIdx.x;
    float acc;
    if (blk < 256) {
        float v = g_minx[blk * 256 + tid];
        acc = fmaxf(2.0f * v, 0.0f);
    } else {
        const size_t idx = (size_t)(blk - 256) * 256 + tid;   // b*MM + m
        float v = CUDART_INF_F;
#pragma unroll 8
        for (int r = 0; r < NUM_RB; r++)
            v = fminf(v, g_cpart[(size_t)r * (BB * MM) + idx]);
        acc = fmaxf(2.0f * v, 0.0f);
    }
    sred[tid] = acc;
    __syncthreads();
    for (int o = 128; o >= 1; o >>= 1) {
        if (tid < o) sred[tid] += sred[tid + o];
        __syncthreads();
    }
    if (tid == 0) g_part[blk] = sred[0];
}

__global__ void final_kernel(float* __restrict__ out) {
    __shared__ float sred[256];
    const int tid = threadIdx.x;
    sred[tid] = g_part[tid] + g_part[tid + 256];
    __syncthreads();
    for (int o = 128; o >= 1; o >>= 1) {
        if (tid < o) sred[tid] += sred[tid + o];
        __syncthreads();
    }
    // cham_x + cham_y, each mean over B*N = B*M = 65536 points.
    if (tid == 0) out[0] = sred[0] * (1.0f / 65536.0f);
}

extern "C" void kernel_launch(void* const* d_in, const int* in_sizes, int n_in,
                              void* d_out, int out_size) {
    const float* gts   = (const float*)d_in[0];
    const float* preds = (const float*)d_in[1];
    float* out = (float*)d_out;

    prep_kernel<<<(BB * NN + 255) / 256, 256>>>(gts, preds);
    chamfer_main_kernel<<<BB * NUM_RB, 256>>>();
    reduce_kernel<<<512, 256>>>();
    final_kernel<<<1, 256>>>(out);
}

// round 2
// speedup vs baseline: 1.2271x; 1.2271x over previous
#include <cuda_runtime.h>
#include <math_constants.h>

// Problem shape (fixed by reference): B=8, N=M=8192, D=3, fp32 scalar out.
#define BB 8
#define NN 8192
#define MM 8192
#define RPT 8                        // gt rows per thread
#define ROWS_PER_BLOCK 128           // 16 ty-lanes * RPT
#define NUM_RB (NN / ROWS_PER_BLOCK) // 64 row-blocks per batch
#define STAGE 256                    // preds staged in smem per sync round
#define CHUNK 64                     // cols per inner chunk (16 tx * 4)

typedef unsigned long long u64;

// Static scratch (no allocations allowed).
__device__ float4 g_gt4[BB * NN];                    // (-x,-y,-z, 0.5*|x|^2)
__device__ float4 g_pr4[BB * MM];                    // ( x, y, z, 0.5*|y|^2)
__device__ float  g_minx[BB * NN];                   // per-gt row min (d'=d^2/2)
__device__ float  g_cpart[(size_t)NUM_RB * BB * MM]; // per-rowblock partial col mins
__device__ float  g_part[512];                       // block partial sums

// ---- packed f32x2 helpers (Blackwell FFMA2 path, PTX-only) -----------------
__device__ __forceinline__ u64 bcast2(float v) {
    u64 r; asm("mov.b64 %0, {%1, %1};" : "=l"(r) : "f"(v)); return r;
}
__device__ __forceinline__ u64 add2(u64 a, u64 b) {
    u64 r; asm("add.rn.f32x2 %0, %1, %2;" : "=l"(r) : "l"(a), "l"(b)); return r;
}
__device__ __forceinline__ u64 fma2(u64 a, u64 b, u64 c) {
    u64 r; asm("fma.rn.f32x2 %0, %1, %2, %3;" : "=l"(r) : "l"(a), "l"(b), "l"(c)); return r;
}
__device__ __forceinline__ void unpack2(u64 v, float& lo, float& hi) {
    asm("mov.b64 {%0, %1}, %2;" : "=f"(lo), "=f"(hi) : "l"(v));
}

// ---------------------------------------------------------------------------
// Pack points into float4 with w = 0.5*norm^2; negate gt coords so the inner
// loop is pure FMA:  d' = gw + pw + (-gx)*px + (-gy)*py + (-gz)*pz = d^2/2.
// ---------------------------------------------------------------------------
__global__ void prep_kernel(const float* __restrict__ gts,
                            const float* __restrict__ preds) {
    int i = blockIdx.x * blockDim.x + threadIdx.x;
    if (i < BB * NN) {
        float x = gts[3 * i + 0], y = gts[3 * i + 1], z = gts[3 * i + 2];
        g_gt4[i] = make_float4(-x, -y, -z, 0.5f * (x * x + y * y + z * z));
    }
    if (i < BB * MM) {
        float x = preds[3 * i + 0], y = preds[3 * i + 1], z = preds[3 * i + 2];
        g_pr4[i] = make_float4(x, y, z, 0.5f * (x * x + y * y + z * z));
    }
}

// ---------------------------------------------------------------------------
// Main fused kernel. Block = (batch b, 128-row block). Iterates all M preds.
// Inner math is packed f32x2 over column pairs: per 2 point-pairs it costs
// 1 add.f32x2 + 3 fma.f32x2 (fma pipe) + 4 FMNMX (alu pipe).
// Thread layout: tx = tid/16 owns 4 columns per chunk; ty = tid%16 row group.
// ---------------------------------------------------------------------------
__global__ void __launch_bounds__(256, 2) chamfer_main_kernel() {
    __shared__ alignas(16) float sx[STAGE], sy[STAGE], sz[STAGE], sw[STAGE];
    __shared__ float scol[16][STAGE + 4];        // +4 pad: stride 260 floats
    __shared__ float rowred[16][ROWS_PER_BLOCK];

    const int tid = threadIdx.x;
    const int tx = tid >> 4;    // 0..15 column group
    const int ty = tid & 15;    // 0..15 row lane
    const int b  = blockIdx.x / NUM_RB;
    const int rb = blockIdx.x % NUM_RB;
    const int rowbase = rb * ROWS_PER_BLOCK;
    const size_t cpart_base = (size_t)rb * (BB * MM) + (size_t)b * MM;

    // Persistent packed gt broadcasts: {v,v} per component per row.
    u64 gx2[RPT], gy2[RPT], gz2[RPT], gw2[RPT];
    float rmin[RPT];
#pragma unroll
    for (int i = 0; i < RPT; i++) {
        float4 g = g_gt4[b * NN + rowbase + ty + 16 * i];
        gx2[i] = bcast2(g.x); gy2[i] = bcast2(g.y);
        gz2[i] = bcast2(g.z); gw2[i] = bcast2(g.w);
        rmin[i] = CUDART_INF_F;
    }

    for (int s = 0; s < MM; s += STAGE) {
        __syncthreads();                         // sp + scol free for reuse
        {   // SoA stage of 256 preds
            float4 p = g_pr4[b * MM + s + tid];
            sx[tid] = p.x; sy[tid] = p.y; sz[tid] = p.z; sw[tid] = p.w;
        }
        __syncthreads();

#pragma unroll
        for (int c = 0; c < STAGE / CHUNK; c++) {
            const int colb = c * CHUNK + tx * 4;
            // Two packed column-pairs, loaded directly as b64 (no pack ops).
            const u64 px0 = *(const u64*)(sx + colb), px1 = *(const u64*)(sx + colb + 2);
            const u64 py0 = *(const u64*)(sy + colb), py1 = *(const u64*)(sy + colb + 2);
            const u64 pz0 = *(const u64*)(sz + colb), pz1 = *(const u64*)(sz + colb + 2);
            const u64 pw0 = *(const u64*)(sw + colb), pw1 = *(const u64*)(sw + colb + 2);
            float cm0 = CUDART_INF_F, cm1 = CUDART_INF_F;
            float cm2 = CUDART_INF_F, cm3 = CUDART_INF_F;
#pragma unroll
            for (int i = 0; i < RPT; i++) {
                u64 t0 = add2(gw2[i], pw0);
                t0 = fma2(gx2[i], px0, t0);
                t0 = fma2(gy2[i], py0, t0);
                t0 = fma2(gz2[i], pz0, t0);
                u64 t1 = add2(gw2[i], pw1);
                t1 = fma2(gx2[i], px1, t1);
                t1 = fma2(gy2[i], py1, t1);
                t1 = fma2(gz2[i], pz1, t1);
                float l0, h0, l1, h1;
                unpack2(t0, l0, h0);
                unpack2(t1, l1, h1);
                cm0 = fminf(cm0, l0); cm1 = fminf(cm1, h0);
                cm2 = fminf(cm2, l1); cm3 = fminf(cm3, h1);
                rmin[i] = fminf(rmin[i], fminf(fminf(l0, h0), fminf(l1, h1)));
            }
            scol[ty][colb + 0] = cm0;
            scol[ty][colb + 1] = cm1;
            scol[ty][colb + 2] = cm2;
            scol[ty][colb + 3] = cm3;
        }
        __syncthreads();

        // Per-stage cooperative column reduce: one column per thread.
        {
            float v = scol[0][tid];
#pragma unroll
            for (int k = 1; k < 16; k++) v = fminf(v, scol[k][tid]);
            g_cpart[cpart_base + s + tid] = v;
        }
    }

    // Finalize row mins: reduce across the 16 tx groups.
#pragma unroll
    for (int i = 0; i < RPT; i++) rowred[tx][ty + 16 * i] = rmin[i];
    __syncthreads();
    if (tid < ROWS_PER_BLOCK) {
        float v = rowred[0][tid];
#pragma unroll
        for (int k = 1; k < 16; k++) v = fminf(v, rowred[k][tid]);
        g_minx[b * NN + rowbase + tid] = v;
    }
}

// ---------------------------------------------------------------------------
// Reduce: blocks 0..255 sum row mins; blocks 256..511 min-reduce the 64
// row-block partials per pred column, then sum. Deterministic trees.
// d' = d^2/2; contribution = max(2*d', 0) (matches reference clamp).
// ---------------------------------------------------------------------------
__global__ void reduce_kernel() {
    __shared__ float sred[256];
    const int blk = blockIdx.x;
    const int tid = threadIdx.x;
    float acc;
    if (blk < 256) {
        float v = g_minx[blk * 256 + tid];
        acc = fmaxf(2.0f * v, 0.0f);
    } else {
        const size_t idx = (size_t)(blk - 256) * 256 + tid;   // b*MM + m
        float v = CUDART_INF_F;
#pragma unroll 8
        for (int r = 0; r < NUM_RB; r++)
            v = fminf(v, g_cpart[(size_t)r * (BB * MM) + idx]);
        acc = fmaxf(2.0f * v, 0.0f);
    }
    sred[tid] = acc;
    __syncthreads();
    for (int o = 128; o >= 1; o >>= 1) {
        if (tid < o) sred[tid] += sred[tid + o];
        __syncthreads();
    }
    if (tid == 0) g_part[blk] = sred[0];
}

__global__ void final_kernel(float* __restrict__ out) {
    __shared__ float sred[256];
    const int tid = threadIdx.x;
    sred[tid] = g_part[tid] + g_part[tid + 256];
    __syncthreads();
    for (int o = 128; o >= 1; o >>= 1) {
        if (tid < o) sred[tid] += sred[tid + o];
        __syncthreads();
    }
    // cham_x + cham_y, each a mean over B*N = B*M = 65536 points.
    if (tid == 0) out[0] = sred[0] * (1.0f / 65536.0f);
}

extern "C" void kernel_launch(void* const* d_in, const int* in_sizes, int n_in,
                              void* d_out, int out_size) {
    const float* gts   = (const float*)d_in[0];
    const float* preds = (const float*)d_in[1];
    float* out = (float*)d_out;

    prep_kernel<<<(BB * NN + 255) / 256, 256>>>(gts, preds);
    chamfer_main_kernel<<<BB * NUM_RB, 256>>>();
    reduce_kernel<<<512, 256>>>();
    final_kernel<<<1, 256>>>(out);
}